// round 14
// baseline (speedup 1.0000x reference)
#include <cuda_runtime.h>
#include <cuda_fp16.h>

#define B_SZ    512
#define FEATS   30
#define NNZ     (B_SZ * FEATS)
#define FT_OUT  512
#define N_FEAT  40960
#define N_VFEAT 640
#define KPAIRS  (FT_OUT / 2)    // 256
#define NRED    16              // last NRED CTAs perform the final reduction

// Packed indices, feature-major: g_packed[f*B + b] = stm_col | (nstm_col<<16)
__device__ unsigned g_packed[NNZ];
__device__ __half   g_vals[NNZ];          // values, feature-major, fp16
// Partial outputs, [k][b] layout -> coalesced stores and reads. 1 MB.
__device__ float    g_partial[FT_OUT * B_SZ];
// Completion ticket counter (zeroed by the pack prepass every launch).
__device__ unsigned g_ticket;

// Dynamic smem: __half2 sft2[N_FEAT] (pair-interleaved fused table, 160 KB),
//               __half2 sfft2[N_VFEAT] (2.5 KB). Reused for the reduce tree.
#define SMEM_BYTES ((N_FEAT + N_VFEAT) * 4)

static __device__ __forceinline__ unsigned h2u(__half2 h) {
    return *reinterpret_cast<unsigned*>(&h);
}
static __device__ __forceinline__ __half2 u2h(unsigned u) {
    return *reinterpret_cast<__half2*>(&u);
}

// ---------------------------------------------------------------------------
// Kernel 0: prepass. Pack cols into u32, values into fp16, feature-major.
// Also resets the ticket counter. Triggers PDL completion immediately so the
// main kernel starts streaming ft_w concurrently.
// ---------------------------------------------------------------------------
__global__ void __launch_bounds__(256) pack_idx_kernel(
    const int*   __restrict__ stm_idx,    // [2, NNZ]; cols at offset NNZ
    const int*   __restrict__ nstm_idx,   // [2, NNZ]
    const float* __restrict__ values)     // [NNZ]
{
    cudaTriggerProgrammaticLaunchCompletion();

    if (blockIdx.x == 0 && threadIdx.x == 0) g_ticket = 0u;

    const int e = blockIdx.x * 256 + threadIdx.x;
    if (e >= NNZ) return;
    const int b = e / FEATS;
    const int f = e % FEATS;
    const unsigned cs = (unsigned)stm_idx [NNZ + e];
    const unsigned cn = (unsigned)nstm_idx[NNZ + e];
    const int dst = f * B_SZ + b;
    g_packed[dst] = cs | (cn << 16);
    g_vals[dst]   = __float2half(values[e]);
}

// ---------------------------------------------------------------------------
// Kernel 1: one CTA per k-PAIR (256 CTAs, 512 threads, 1 CTA/SM, 163KB smem).
// Phase A: fft_w rows {k0, k0+1} -> smem, pair-interleaved half2.
// Phase B: stream ft_w rows {k0, k0+1}; sft2[c] = (ft[k0][c]+fft[k0][c%640],
//          ft[k1][c]+fft[k1][c%640]). fft offsets have period 5 -> reg cache.
// (PDL grid sync before Phase C.)
// Phase C: thread t = batch row t; one random LDS.32 serves BOTH k's.
// Tail   : threadfence + ticket; the last NRED CTAs spin until all partials
//          are stored, then reduce 32 batch rows each + sigmoid (in-kernel
//          replacement for the separate reduce kernel).
// ---------------------------------------------------------------------------
__global__ void __launch_bounds__(512, 1) halfkp_pair_kernel(
    const float* __restrict__ ft_w,      // [512, 40960]
    const float* __restrict__ ft_b,      // [512]
    const float* __restrict__ fft_w,     // [512, 640]
    const float* __restrict__ fft_b,     // [512]
    const float* __restrict__ out_w,     // [1, 1024]
    const float* __restrict__ out_b,     // [1]
    float*       __restrict__ out)       // [512]
{
    extern __shared__ char smem_raw[];
    __half2* sft2  = reinterpret_cast<__half2*>(smem_raw);   // [N_FEAT]
    __half2* sfft2 = sft2 + N_FEAT;                          // [N_VFEAT]

    const int kp = blockIdx.x;
    const int k0 = 2 * kp;
    const int t  = threadIdx.x;

    // ---- Phase A: fft rows pair-interleaved ----
    if (t < N_VFEAT / 4) {   // 160 threads, one float4 per row each
        float4 a = __ldg(reinterpret_cast<const float4*>(
                             fft_w + (size_t)k0 * N_VFEAT) + t);
        float4 b = __ldg(reinterpret_cast<const float4*>(
                             fft_w + (size_t)(k0 + 1) * N_VFEAT) + t);
        uint4 p;
        p.x = h2u(__floats2half2_rn(a.x, b.x));
        p.y = h2u(__floats2half2_rn(a.y, b.y));
        p.z = h2u(__floats2half2_rn(a.z, b.z));
        p.w = h2u(__floats2half2_rn(a.w, b.w));
        reinterpret_cast<uint4*>(sfft2)[t] = p;
    }
    __syncthreads();

    // ---- Phase B: stream both rows, fuse fft, store pair-interleaved ----
    {
        // fft offset m_i = (4t + 2048 i) % 640 has period 5 (2048%640=128).
        uint4 fc[5];
        #pragma unroll
        for (int j = 0; j < 5; j++) {
            const int m = (4 * t + 128 * j) % N_VFEAT;   // multiple of 4
            fc[j] = *reinterpret_cast<const uint4*>(sfft2 + m);
        }

        const float4* r0 = reinterpret_cast<const float4*>(
                               ft_w + (size_t)k0 * N_FEAT);
        const float4* r1 = reinterpret_cast<const float4*>(
                               ft_w + (size_t)(k0 + 1) * N_FEAT);
        #pragma unroll
        for (int i = 0; i < N_FEAT / 4 / 512; i++) {     // 20 iterations
            const int idx = t + i * 512;
            const int c   = idx * 4;                      // half2 column
            const uint4 f = fc[i % 5];                    // static per unroll
            float4 a = __ldg(r0 + idx);
            float4 b = __ldg(r1 + idx);
            uint4 p;
            p.x = h2u(__hadd2(__floats2half2_rn(a.x, b.x), u2h(f.x)));
            p.y = h2u(__hadd2(__floats2half2_rn(a.y, b.y), u2h(f.y)));
            p.z = h2u(__hadd2(__floats2half2_rn(a.z, b.z), u2h(f.z)));
            p.w = h2u(__hadd2(__floats2half2_rn(a.w, b.w), u2h(f.w)));
            *reinterpret_cast<uint4*>(sft2 + c) = p;      // STS.128 coalesced
        }
    }
    __syncthreads();

    // PDL: packed index data must be complete (and visible) before Phase C.
    cudaGridDependencySynchronize();

    // ---- Phase C: thread t = batch row t; one LDS.32 serves both k's ----
    float2 accs = make_float2(0.f, 0.f);
    float2 accn = make_float2(0.f, 0.f);

    #pragma unroll
    for (int c = 0; c < 3; c++) {                         // chunks of 10
        unsigned p[10];
        __half   v[10];
        #pragma unroll
        for (int f = 0; f < 10; f++) {
            const int idx = (c * 10 + f) * B_SZ + t;      // lane-consecutive
            p[f] = __ldg(g_packed + idx);
            v[f] = g_vals[idx];
        }
        #pragma unroll
        for (int f = 0; f < 10; f++) {
            const float vf = __half2float(v[f]);
            float2 ws = __half22float2(sft2[p[f] & 0xFFFFu]);
            float2 wn = __half22float2(sft2[p[f] >> 16]);
            accs.x = fmaf(vf, ws.x, accs.x);
            accs.y = fmaf(vf, ws.y, accs.y);
            accn.x = fmaf(vf, wn.x, accn.x);
            accn.y = fmaf(vf, wn.y, accn.y);
        }
    }

    // ---- Epilogue: bias + clip + out_w partials for k0 and k1 ----
    const float b0 = __ldg(ft_b + k0)     + __ldg(fft_b + k0);
    const float b1 = __ldg(ft_b + k0 + 1) + __ldg(fft_b + k0 + 1);
    const float w0 = __ldg(out_w + k0);
    const float w1 = __ldg(out_w + k0 + 1);
    const float u0 = __ldg(out_w + FT_OUT + k0);
    const float u1 = __ldg(out_w + FT_OUT + k0 + 1);

    g_partial[(size_t)k0 * B_SZ + t] =
        w0 * __saturatef(accs.x + b0) + u0 * __saturatef(accn.x + b0);
    g_partial[(size_t)(k0 + 1) * B_SZ + t] =
        w1 * __saturatef(accs.y + b1) + u1 * __saturatef(accn.y + b1);

    // ---- Tail: last-NRED-CTAs fused reduction (threadFenceReduction) ----
    __threadfence();                       // release partial stores
    __shared__ unsigned s_tick;
    if (t == 0) s_tick = atomicAdd(&g_ticket, 1u);
    __syncthreads();
    const unsigned tick = s_tick;

    if (tick >= KPAIRS - NRED) {
        if (t == 0) {
            while (atomicAdd(&g_ticket, 0u) < KPAIRS) { __nanosleep(64); }
        }
        __syncthreads();                   // all partials now stored+fenced

        const int slice = (int)tick - (KPAIRS - NRED);   // 0..15
        const int tx = t & 31;             // batch lane
        const int ty = t >> 5;             // k group (0..15), 32 k's each
        const int b  = slice * 32 + tx;

        float s = 0.f;
        #pragma unroll 8
        for (int i = 0; i < FT_OUT / 16; i++)            // 32 coalesced loads
            s += g_partial[(ty * (FT_OUT / 16) + i) * B_SZ + b];

        float* red = reinterpret_cast<float*>(smem_raw); // reuse dead table
        red[ty * 33 + tx] = s;
        __syncthreads();

        if (ty == 0) {
            float tot = __ldg(out_b);
            #pragma unroll
            for (int j = 0; j < 16; j++) tot += red[j * 33 + tx];
            out[b] = 1.0f / (1.0f + expf(-tot));
        }
    }
}

// ---------------------------------------------------------------------------
extern "C" void kernel_launch(void* const* d_in, const int* in_sizes, int n_in,
                              void* d_out, int out_size) {
    const int*   stm_idx  = (const int*)  d_in[0];
    const int*   nstm_idx = (const int*)  d_in[1];
    const float* values   = (const float*)d_in[2];
    const float* ft_w     = (const float*)d_in[3];
    const float* ft_b     = (const float*)d_in[4];
    const float* fft_w    = (const float*)d_in[5];
    const float* fft_b    = (const float*)d_in[6];
    const float* out_w    = (const float*)d_in[7];
    const float* out_b    = (const float*)d_in[8];
    float*       out      = (float*)d_out;

    (void)in_sizes; (void)n_in; (void)out_size;

    cudaFuncSetAttribute(halfkp_pair_kernel,
                         cudaFuncAttributeMaxDynamicSharedMemorySize, SMEM_BYTES);

    pack_idx_kernel<<<(NNZ + 255) / 256, 256>>>(stm_idx, nstm_idx, values);

    // Main kernel with PDL: overlaps with the pack kernel; includes the
    // fused final reduction (no separate reduce kernel).
    {
        cudaLaunchConfig_t cfg = {};
        cfg.gridDim          = dim3(KPAIRS);
        cfg.blockDim         = dim3(512);
        cfg.dynamicSmemBytes = SMEM_BYTES;
        cfg.stream           = 0;
        cudaLaunchAttribute at[1];
        at[0].id = cudaLaunchAttributeProgrammaticStreamSerialization;
        at[0].val.programmaticStreamSerializationAllowed = 1;
        cfg.attrs    = at;
        cfg.numAttrs = 1;
        cudaLaunchKernelEx(&cfg, halfkp_pair_kernel,
                           ft_w, ft_b, fft_w, fft_b, out_w, out_b, out);
    }
}

// round 15
// speedup vs baseline: 1.0976x; 1.0976x over previous
#include <cuda_runtime.h>
#include <cuda_fp16.h>

#define B_SZ    512
#define FEATS   30
#define NNZ     (B_SZ * FEATS)
#define FT_OUT  512
#define N_FEAT  40960
#define N_VFEAT 640
#define KPAIRS  (FT_OUT / 2)    // 256

// Packed indices, feature-major: g_packed[f*B + b] = stm_col | (nstm_col<<16)
__device__ unsigned g_packed[NNZ];
__device__ __half   g_vals[NNZ];          // values, feature-major, fp16
// Atomic output accumulator [b] and completion ticket (zeroed by prepass).
__device__ float    g_acc[B_SZ];
__device__ unsigned g_ticket;

// Dynamic smem: __half2 sft2[N_FEAT] (pair-interleaved fused table, 160 KB),
//               __half2 sfft2[N_VFEAT] (2.5 KB)
#define SMEM_BYTES ((N_FEAT + N_VFEAT) * 4)

static __device__ __forceinline__ unsigned h2u(__half2 h) {
    return *reinterpret_cast<unsigned*>(&h);
}
static __device__ __forceinline__ __half2 u2h(unsigned u) {
    return *reinterpret_cast<__half2*>(&u);
}

// ---------------------------------------------------------------------------
// Kernel 0: prepass. Pack cols into u32, values into fp16, feature-major.
// Zeroes the output accumulator and ticket. Triggers PDL completion
// immediately so the main kernel starts streaming ft_w concurrently.
// ---------------------------------------------------------------------------
__global__ void __launch_bounds__(256) pack_idx_kernel(
    const int*   __restrict__ stm_idx,    // [2, NNZ]; cols at offset NNZ
    const int*   __restrict__ nstm_idx,   // [2, NNZ]
    const float* __restrict__ values)     // [NNZ]
{
    cudaTriggerProgrammaticLaunchCompletion();

    const int e = blockIdx.x * 256 + threadIdx.x;
    if (e < B_SZ) g_acc[e] = 0.0f;
    if (e == 0)   g_ticket = 0u;
    if (e >= NNZ) return;

    const int b = e / FEATS;
    const int f = e % FEATS;
    const unsigned cs = (unsigned)stm_idx [NNZ + e];
    const unsigned cn = (unsigned)nstm_idx[NNZ + e];
    const int dst = f * B_SZ + b;
    g_packed[dst] = cs | (cn << 16);
    g_vals[dst]   = __float2half(values[e]);
}

// ---------------------------------------------------------------------------
// Kernel 1: one CTA per k-PAIR (256 CTAs, 512 threads, 1 CTA/SM, 163KB smem).
// Phase A: fft_w rows {k0, k0+1} -> smem, pair-interleaved half2.
// Phase B: stream ft_w rows {k0, k0+1}; sft2[c] = (ft[k0][c]+fft[k0][c%640],
//          ft[k1][c]+fft[k1][c%640]). fft offsets have period 5 -> reg cache.
// (PDL grid sync before Phase C.)
// Phase C: thread t = batch row t; one random LDS.32 serves BOTH k's.
// Tail   : combine both k contributions into ONE float, atomicAdd to
//          g_acc[t]; last-ticket CTA applies out_b + sigmoid and stores out.
// ---------------------------------------------------------------------------
__global__ void __launch_bounds__(512, 1) halfkp_pair_kernel(
    const float* __restrict__ ft_w,      // [512, 40960]
    const float* __restrict__ ft_b,      // [512]
    const float* __restrict__ fft_w,     // [512, 640]
    const float* __restrict__ fft_b,     // [512]
    const float* __restrict__ out_w,     // [1, 1024]
    const float* __restrict__ out_b,     // [1]
    float*       __restrict__ out)       // [512]
{
    extern __shared__ char smem_raw[];
    __half2* sft2  = reinterpret_cast<__half2*>(smem_raw);   // [N_FEAT]
    __half2* sfft2 = sft2 + N_FEAT;                          // [N_VFEAT]

    const int kp = blockIdx.x;
    const int k0 = 2 * kp;
    const int t  = threadIdx.x;

    // ---- Phase A: fft rows pair-interleaved ----
    if (t < N_VFEAT / 4) {   // 160 threads, one float4 per row each
        float4 a = __ldg(reinterpret_cast<const float4*>(
                             fft_w + (size_t)k0 * N_VFEAT) + t);
        float4 b = __ldg(reinterpret_cast<const float4*>(
                             fft_w + (size_t)(k0 + 1) * N_VFEAT) + t);
        uint4 p;
        p.x = h2u(__floats2half2_rn(a.x, b.x));
        p.y = h2u(__floats2half2_rn(a.y, b.y));
        p.z = h2u(__floats2half2_rn(a.z, b.z));
        p.w = h2u(__floats2half2_rn(a.w, b.w));
        reinterpret_cast<uint4*>(sfft2)[t] = p;
    }
    __syncthreads();

    // ---- Phase B: stream both rows, fuse fft, store pair-interleaved ----
    {
        // fft offset m_i = (4t + 2048 i) % 640 has period 5 (2048%640=128).
        uint4 fc[5];
        #pragma unroll
        for (int j = 0; j < 5; j++) {
            const int m = (4 * t + 128 * j) % N_VFEAT;   // multiple of 4
            fc[j] = *reinterpret_cast<const uint4*>(sfft2 + m);
        }

        const float4* r0 = reinterpret_cast<const float4*>(
                               ft_w + (size_t)k0 * N_FEAT);
        const float4* r1 = reinterpret_cast<const float4*>(
                               ft_w + (size_t)(k0 + 1) * N_FEAT);
        #pragma unroll
        for (int i = 0; i < N_FEAT / 4 / 512; i++) {     // 20 iterations
            const int idx = t + i * 512;
            const int c   = idx * 4;                      // half2 column
            const uint4 f = fc[i % 5];                    // static per unroll
            float4 a = __ldg(r0 + idx);
            float4 b = __ldg(r1 + idx);
            uint4 p;
            p.x = h2u(__hadd2(__floats2half2_rn(a.x, b.x), u2h(f.x)));
            p.y = h2u(__hadd2(__floats2half2_rn(a.y, b.y), u2h(f.y)));
            p.z = h2u(__hadd2(__floats2half2_rn(a.z, b.z), u2h(f.z)));
            p.w = h2u(__hadd2(__floats2half2_rn(a.w, b.w), u2h(f.w)));
            *reinterpret_cast<uint4*>(sft2 + c) = p;      // STS.128 coalesced
        }
    }
    __syncthreads();

    // PDL: packed index data (and zeroed g_acc) visible before Phase C.
    cudaGridDependencySynchronize();

    // ---- Phase C: thread t = batch row t; one LDS.32 serves both k's ----
    float2 accs = make_float2(0.f, 0.f);
    float2 accn = make_float2(0.f, 0.f);

    #pragma unroll
    for (int c = 0; c < 3; c++) {                         // chunks of 10
        unsigned p[10];
        __half   v[10];
        #pragma unroll
        for (int f = 0; f < 10; f++) {
            const int idx = (c * 10 + f) * B_SZ + t;      // lane-consecutive
            p[f] = __ldg(g_packed + idx);
            v[f] = g_vals[idx];
        }
        #pragma unroll
        for (int f = 0; f < 10; f++) {
            const float vf = __half2float(v[f]);
            float2 ws = __half22float2(sft2[p[f] & 0xFFFFu]);
            float2 wn = __half22float2(sft2[p[f] >> 16]);
            accs.x = fmaf(vf, ws.x, accs.x);
            accs.y = fmaf(vf, ws.y, accs.y);
            accn.x = fmaf(vf, wn.x, accn.x);
            accn.y = fmaf(vf, wn.y, accn.y);
        }
    }

    // ---- Epilogue: bias + clip + out_w; both k's folded into one float ----
    const float b0 = __ldg(ft_b + k0)     + __ldg(fft_b + k0);
    const float b1 = __ldg(ft_b + k0 + 1) + __ldg(fft_b + k0 + 1);
    const float w0 = __ldg(out_w + k0);
    const float w1 = __ldg(out_w + k0 + 1);
    const float u0 = __ldg(out_w + FT_OUT + k0);
    const float u1 = __ldg(out_w + FT_OUT + k0 + 1);

    const float part = w0 * __saturatef(accs.x + b0)
                     + u0 * __saturatef(accn.x + b0)
                     + w1 * __saturatef(accs.y + b1)
                     + u1 * __saturatef(accn.y + b1);

    atomicAdd(&g_acc[t], part);           // spread addresses, L2-resident

    // ---- Tail: last-ticket CTA applies sigmoid and writes the output ----
    __threadfence();                       // order adds before ticket
    __shared__ unsigned s_tick;
    if (t == 0) s_tick = atomicAdd(&g_ticket, 1u);
    __syncthreads();

    if (s_tick == KPAIRS - 1) {            // last CTA to finish
        if (t == 0) {
            while (atomicAdd(&g_ticket, 0u) < KPAIRS) { __nanosleep(32); }
        }
        __syncthreads();                   // all 256 CTAs' adds visible
        const float ob = __ldg(out_b);
        const float s  = *((volatile float*)&g_acc[t]);
        out[t] = 1.0f / (1.0f + expf(-(s + ob)));
    }
}

// ---------------------------------------------------------------------------
extern "C" void kernel_launch(void* const* d_in, const int* in_sizes, int n_in,
                              void* d_out, int out_size) {
    const int*   stm_idx  = (const int*)  d_in[0];
    const int*   nstm_idx = (const int*)  d_in[1];
    const float* values   = (const float*)d_in[2];
    const float* ft_w     = (const float*)d_in[3];
    const float* ft_b     = (const float*)d_in[4];
    const float* fft_w    = (const float*)d_in[5];
    const float* fft_b    = (const float*)d_in[6];
    const float* out_w    = (const float*)d_in[7];
    const float* out_b    = (const float*)d_in[8];
    float*       out      = (float*)d_out;

    (void)in_sizes; (void)n_in; (void)out_size;

    cudaFuncSetAttribute(halfkp_pair_kernel,
                         cudaFuncAttributeMaxDynamicSharedMemorySize, SMEM_BYTES);

    pack_idx_kernel<<<(NNZ + 255) / 256, 256>>>(stm_idx, nstm_idx, values);

    // Main kernel with PDL: overlaps with the pack kernel; the final
    // sigmoid runs in the last-finishing CTA (no reduce kernel at all).
    {
        cudaLaunchConfig_t cfg = {};
        cfg.gridDim          = dim3(KPAIRS);
        cfg.blockDim         = dim3(512);
        cfg.dynamicSmemBytes = SMEM_BYTES;
        cfg.stream           = 0;
        cudaLaunchAttribute at[1];
        at[0].id = cudaLaunchAttributeProgrammaticStreamSerialization;
        at[0].val.programmaticStreamSerializationAllowed = 1;
        cfg.attrs    = at;
        cfg.numAttrs = 1;
        cudaLaunchKernelEx(&cfg, halfkp_pair_kernel,
                           ft_w, ft_b, fft_w, fft_b, out_w, out_b, out);
    }
}